// round 15
// baseline (speedup 1.0000x reference)
#include <cuda_runtime.h>
#include <cuda_bf16.h>
#include <cstdint>

// ---------------------------------------------------------------------------
// MetricLoss: x [1024, 64, 768] fp32 -> (loss_homo_scaled, loss_heter_scaled)
//   f = x.reshape(1024, 49152)
//   dist[j,k] = max(||f_j||^2 + ||f_k||^2 - 2 f_j.f_k, 0)
//   homo  = sum over unordered same-group pairs of dist        (groups of 8)
//   heter = sum over ORDERED diff-group pairs of max(1-dist,0)
// Strategy: bf16 Gram via mma.sync (sm_100 base: NO tcgen05), lower triangle,
// split-K=8, warp-decoupled mainloop (warp-private smem stages, per-warp
// cp.async waits, zero block barriers).  This round: INTERLEAVED fragment
// pipeline -- each 16-k step = 4 quarters of [2 ldmatrix for NEXT step +
// 8 mma for current step], so the warp never sits in a pure-ldmatrix phase
// (R14 profile: tensor 75%, bubbles at step heads).  fp32 accum,
// deterministic reductions.  k_convert split x3 so ncu -s 5 lands on k_gemm.
// ---------------------------------------------------------------------------

#define N_ROWS   1024
#define KDIM     49152                 // 64 * 768
#define BK_GROUP 8
#define NGROUPS  (N_ROWS / BK_GROUP)   // 128

#define BM 128
#define BN 128
#define BKC 32                         // k per stage
#define STAGES 3
#define SPLITK 8
#define KSPLIT (KDIM / SPLITK)         // 6144
#define NITER  (KSPLIT / BKC)          // 192
#define NTB    (N_ROWS / BM)           // 8
#define NTILES (NTB * (NTB + 1) / 2)   // 36
#define LPARTS 4                       // k_loss row-slices per tile

#define SUB_BYTES   4096               // 64 rows x 64B (one warp's A or B half)
#define WARP_STAGE  (2 * SUB_BYTES)    // A + B per warp per stage = 8 KB
#define STAGE_BYTES (4 * WARP_STAGE)   // 4 warps = 32 KB
#define SMEM_BYTES  (STAGES * STAGE_BYTES)   // 98304 (x2 CTAs = 192K <= 228K)

// Scratch (device globals: allocation-free per harness rules)
__device__ __align__(128) __nv_bfloat16 g_fbf[(size_t)N_ROWS * KDIM]; // 96 MiB
__device__ float g_sq[N_ROWS];
__device__ float g_part[(size_t)NTILES * SPLITK * BM * BN];
__device__ float g_tileloss[NTILES][LPARTS][2];

// ---------------------------------------------------------------------------
// K1: fp32 -> bf16 conversion + per-row squared norm (row-chunk version)
// ---------------------------------------------------------------------------
__global__ __launch_bounds__(512) void k_convert(const float* __restrict__ x,
                                                 int row_base) {
    const int row = row_base + blockIdx.x;
    const float* xr = x + (size_t)row * KDIM;
    __nv_bfloat16* fr = g_fbf + (size_t)row * KDIM;

    float s = 0.0f;
    for (int i = threadIdx.x * 4; i < KDIM; i += blockDim.x * 4) {
        float4 v = *reinterpret_cast<const float4*>(xr + i);
        s += v.x * v.x + v.y * v.y + v.z * v.z + v.w * v.w;
        __nv_bfloat162 lo = __floats2bfloat162_rn(v.x, v.y);
        __nv_bfloat162 hi = __floats2bfloat162_rn(v.z, v.w);
        uint2 packed;
        packed.x = *reinterpret_cast<uint32_t*>(&lo);
        packed.y = *reinterpret_cast<uint32_t*>(&hi);
        *reinterpret_cast<uint2*>(fr + i) = packed;
    }

    __shared__ float red[16];
    int lane = threadIdx.x & 31, warp = threadIdx.x >> 5;
    #pragma unroll
    for (int o = 16; o; o >>= 1) s += __shfl_xor_sync(0xffffffffu, s, o);
    if (lane == 0) red[warp] = s;
    __syncthreads();
    if (warp == 0) {
        float v = (lane < 16) ? red[lane] : 0.0f;
        #pragma unroll
        for (int o = 8; o; o >>= 1) v += __shfl_xor_sync(0xffffffffu, v, o);
        if (lane == 0) g_sq[row] = v;
    }
}

// ---------------------------------------------------------------------------
// K2: warp-decoupled bf16 Gram, interleaved fragment pipeline
// ---------------------------------------------------------------------------
__device__ __forceinline__ uint32_t smem_u32(const void* p) {
    return (uint32_t)__cvta_generic_to_shared(p);
}
__device__ __forceinline__ void cp16(uint32_t dst, const void* src) {
    asm volatile("cp.async.cg.shared.global [%0], [%1], 16;\n" :: "r"(dst), "l"(src));
}
// swizzled byte offset inside a 64-row x 64B sub-panel; r = row, c = 16B col
__device__ __forceinline__ uint32_t swz(int r, int c) {
    return (uint32_t)(r * 64 + ((c ^ (r & 3) ^ ((r >> 2) & 1)) << 4));
}

__global__ __launch_bounds__(128, 2) void k_gemm() {
    extern __shared__ __align__(128) char smem[];

    const int t = blockIdx.x;       // 0..35 (lower-tri tile index)
    const int split = blockIdx.y;   // 0..7

    int bi = 0;
    while ((bi + 1) * (bi + 2) / 2 <= t) bi++;
    const int bj = t - bi * (bi + 1) / 2;

    const int k_begin = split * KSPLIT;

    const int tid  = threadIdx.x;
    const int warp = tid >> 5;
    const int lane = tid & 31;
    const int wm = warp >> 1;           // 0..1 -> 64-row A half
    const int wn = warp & 1;            // 0..1 -> 64-row B half
    const int arow0 = bi * BM + wm * 64;
    const int brow0 = bj * BN + wn * 64;

    float acc[4][8][4];
    #pragma unroll
    for (int im = 0; im < 4; im++)
        #pragma unroll
        for (int in = 0; in < 8; in++)
            #pragma unroll
            for (int e = 0; e < 4; e++) acc[im][in][e] = 0.0f;

    uint32_t sbase[STAGES];
    #pragma unroll
    for (int s = 0; s < STAGES; s++)
        sbase[s] = smem_u32(smem) + (uint32_t)((s * 4 + warp) * WARP_STAGE);

    // cp.async mapping: lane covers rows (lane>>2)+8j (j=0..7), 16B-col lane&3
    const int clr = lane >> 2;
    const int ccc = lane & 3;

    auto load_stage = [&](int s, int k0) {
        const uint32_t ab = sbase[s];
        const uint32_t bb = ab + SUB_BYTES;
        const __nv_bfloat16* ga = &g_fbf[(size_t)(arow0 + clr) * KDIM + k0 + ccc * 8];
        const __nv_bfloat16* gb = &g_fbf[(size_t)(brow0 + clr) * KDIM + k0 + ccc * 8];
        #pragma unroll
        for (int j = 0; j < 8; j++) {
            cp16(ab + swz(clr + 8 * j, ccc), ga + (size_t)(8 * j) * KDIM);
            cp16(bb + swz(clr + 8 * j, ccc), gb + (size_t)(8 * j) * KDIM);
        }
        asm volatile("cp.async.commit_group;\n" ::);
    };

    // ldmatrix lane coords
    const int a_lrb = lane & 15;                      // A row within 16
    const int a_cb  = lane >> 4;                      // A 16B col offset 0/1
    const int b_lrb = (lane & 7) + ((lane >> 1) & 8); // B row within 16
    const int b_cb  = (lane >> 3) & 1;                // B 16B col offset 0/1

    // fragment double buffers
    uint32_t af[2][4][4];
    uint32_t bf[2][4][4];

    // load quarter q (A frag + B frag) into buffer FB from (ab,bb) at 16B col cb
    auto ldm_q = [&](uint32_t (&A)[4][4], uint32_t (&B)[4][4],
                     uint32_t ab, uint32_t bb, int cb, int q) {
        asm volatile(
            "ldmatrix.sync.aligned.m8n8.x4.shared.b16 {%0,%1,%2,%3}, [%4];"
            : "=r"(A[q][0]), "=r"(A[q][1]), "=r"(A[q][2]), "=r"(A[q][3])
            : "r"(ab + swz(q * 16 + a_lrb, cb + a_cb)));
        asm volatile(
            "ldmatrix.sync.aligned.m8n8.x4.trans.shared.b16 {%0,%1,%2,%3}, [%4];"
            : "=r"(B[q][0]), "=r"(B[q][1]), "=r"(B[q][2]), "=r"(B[q][3])
            : "r"(bb + swz(q * 16 + b_lrb, cb + b_cb)));
    };
    // 8 mmas for row-quarter q using fragment buffer (Af, Bf)
    auto mma_q = [&](uint32_t (&A)[4][4], uint32_t (&B)[4][4], int q) {
        #pragma unroll
        for (int in = 0; in < 8; in++) {
            const int inp  = in >> 1;
            const int pair = (in & 1) << 1;
            asm volatile(
                "mma.sync.aligned.m16n8k16.row.col.f32.bf16.bf16.f32 "
                "{%0,%1,%2,%3}, {%4,%5,%6,%7}, {%8,%9}, {%0,%1,%2,%3};"
                : "+f"(acc[q][in][0]), "+f"(acc[q][in][1]),
                  "+f"(acc[q][in][2]), "+f"(acc[q][in][3])
                : "r"(A[q][0]), "r"(A[q][1]), "r"(A[q][2]), "r"(A[q][3]),
                  "r"(B[inp][pair]), "r"(B[inp][pair + 1]));
        }
    };

    // prologue: 3 stages in flight; wait stage 0; preload frags[0] = (s0, k0)
    load_stage(0, k_begin);
    load_stage(1, k_begin + BKC);
    load_stage(2, k_begin + 2 * BKC);
    asm volatile("cp.async.wait_group 2;\n" ::);
    {
        const uint32_t ab = sbase[0];
        const uint32_t bb = ab + SUB_BYTES;
        #pragma unroll
        for (int q = 0; q < 4; q++) ldm_q(af[0], bf[0], ab, bb, 0, q);
    }

    for (int i = 0; i < NITER; i++) {
        const uint32_t ab = sbase[i % STAGES];
        const uint32_t bb = ab + SUB_BYTES;

        // STEP A: mma (stage i, k0) from frags[0]; interleave ldm frags[1] = (stage i, k16)
        #pragma unroll
        for (int q = 0; q < 4; q++) {
            ldm_q(af[1], bf[1], ab, bb, 2, q);
            mma_q(af[0], bf[0], q);
        }

        // refill: stage i+3 into buffer i%3 (this warp's ldms on it are done;
        // the async write lands after a global fetch, far later than any read)
        if (i + 3 < NITER) load_stage(i % STAGES, k_begin + (i + 3) * BKC);
        else asm volatile("cp.async.commit_group;\n" ::);
        // committed: stages 0..i+3 -> allow 2 pending -> stage i+1 ready
        asm volatile("cp.async.wait_group 2;\n" ::);

        // STEP B: mma (stage i, k16) from frags[1]; interleave ldm frags[0] = (stage i+1, k0)
        const int ni = (i + 1 < NITER) ? (i + 1) : i;   // last iter: stale reload, unused
        const uint32_t nab = sbase[ni % STAGES];
        const uint32_t nbb = nab + SUB_BYTES;
        #pragma unroll
        for (int q = 0; q < 4; q++) {
            ldm_q(af[0], bf[0], nab, nbb, 0, q);
            mma_q(af[1], bf[1], q);
        }
    }

    // epilogue: fp32 partial tile per split (deterministic reduce in K3)
    float* out = g_part + ((size_t)t * SPLITK + split) * (BM * BN);
    const int er = lane >> 2;
    const int ec = (lane & 3) << 1;
    const int wrow = wm * 64;
    const int wcol = wn * 64;
    #pragma unroll
    for (int im = 0; im < 4; im++)
        #pragma unroll
        for (int in = 0; in < 8; in++) {
            const int rg = wrow + im * 16 + er;
            const int cg = wcol + in * 8 + ec;
            *reinterpret_cast<float2*>(&out[rg * BN + cg]) =
                make_float2(acc[im][in][0], acc[im][in][1]);
            *reinterpret_cast<float2*>(&out[(rg + 8) * BN + cg]) =
                make_float2(acc[im][in][2], acc[im][in][3]);
        }
}

// ---------------------------------------------------------------------------
// K3: per-tile loss reduction, 4 row-slices per tile (grid 36 x 4)
// ---------------------------------------------------------------------------
__global__ __launch_bounds__(256) void k_loss() {
    const int t = blockIdx.x;
    const int part = blockIdx.y;        // 0..3 -> rows [part*32, part*32+32)
    int bi = 0;
    while ((bi + 1) * (bi + 2) / 2 <= t) bi++;
    const int bj = t - bi * (bi + 1) / 2;

    float homo = 0.0f, heter = 0.0f;
    const float* base = g_part + (size_t)t * SPLITK * (BM * BN);
    const int e0 = part * 32 * BN;

    for (int ee = threadIdx.x; ee < 32 * BN; ee += blockDim.x) {
        const int e = e0 + ee;
        const int rl = e >> 7;
        const int cl = e & 127;
        if (bi == bj && rl <= cl) continue;   // strict lower triangle on diagonal tiles
        float dot = 0.0f;
        #pragma unroll
        for (int s = 0; s < SPLITK; s++) dot += base[(size_t)s * (BM * BN) + e];
        const int j = bi * BM + rl;
        const int k = bj * BN + cl;
        const float dist = fmaxf(g_sq[j] + g_sq[k] - 2.0f * dot, 0.0f);
        if ((j >> 3) == (k >> 3)) homo += dist;                 // same group (size 8)
        else heter += 2.0f * fmaxf(1.0f - dist, 0.0f);          // ordered => x2
    }

    __shared__ float sh[8], se[8];
    const int lane = threadIdx.x & 31, warp = threadIdx.x >> 5;
    #pragma unroll
    for (int o = 16; o; o >>= 1) {
        homo  += __shfl_xor_sync(0xffffffffu, homo, o);
        heter += __shfl_xor_sync(0xffffffffu, heter, o);
    }
    if (lane == 0) { sh[warp] = homo; se[warp] = heter; }
    __syncthreads();
    if (warp == 0) {
        float h = (lane < 8) ? sh[lane] : 0.0f;
        float x = (lane < 8) ? se[lane] : 0.0f;
        #pragma unroll
        for (int o = 4; o; o >>= 1) {
            h += __shfl_xor_sync(0xffffffffu, h, o);
            x += __shfl_xor_sync(0xffffffffu, x, o);
        }
        if (lane == 0) { g_tileloss[t][part][0] = h; g_tileloss[t][part][1] = x; }
    }
}

// ---------------------------------------------------------------------------
// K4: final fixed-order sum + scaling (144 partials)
// ---------------------------------------------------------------------------
__global__ void k_final(float* __restrict__ out) {
    float h = 0.0f, e = 0.0f;
    for (int i = threadIdx.x; i < NTILES * LPARTS; i += 32) {
        h += g_tileloss[i / LPARTS][i % LPARTS][0];
        e += g_tileloss[i / LPARTS][i % LPARTS][1];
    }
    #pragma unroll
    for (int o = 16; o; o >>= 1) {
        h += __shfl_xor_sync(0xffffffffu, h, o);
        e += __shfl_xor_sync(0xffffffffu, e, o);
    }
    if (threadIdx.x == 0) {
        out[0] = 2.0f * h / ((float)N_ROWS * (float)(BK_GROUP - 1));
        out[1] = 2.0f * e / ((float)N_ROWS * (float)(NGROUPS - 1));
    }
}

// ---------------------------------------------------------------------------
extern "C" void kernel_launch(void* const* d_in, const int* in_sizes, int n_in,
                              void* d_out, int out_size) {
    const float* x = (const float*)d_in[0];
    float* out = (float*)d_out;

    cudaFuncSetAttribute(k_gemm, cudaFuncAttributeMaxDynamicSharedMemorySize, SMEM_BYTES);

    // convert split into 3 launches keeps k_gemm as this function's 4th launch
    // so ncu -s 5 -c 1 captures k_gemm.
    k_convert<<<342, 512>>>(x, 0);
    k_convert<<<341, 512>>>(x, 342);
    k_convert<<<341, 512>>>(x, 683);
    dim3 ggrid(NTILES, SPLITK);
    k_gemm<<<ggrid, 128, SMEM_BYTES>>>();
    dim3 lgrid(NTILES, LPARTS);
    k_loss<<<lgrid, 256>>>();
    k_final<<<1, 32>>>(out);
}